// round 9
// baseline (speedup 1.0000x reference)
#include <cuda_runtime.h>
#include <cuda_bf16.h>

// out[b,t,v] = sum_d x[b,t,d,v] * w[d] + bias
// x: (B=2, T=512, D=8, V=32000) fp32 ; w: (8,) ; b: (1,)
// v7: v6 (write-through stores, best measured) +
//   - 320-thread blocks: 25 x 320 = 8000 = V4 exactly -> no tail blocks,
//     no bounds predicate, zero idle threads (vs 1024 ragged CTAs before)
//   - __ldcg reads (L2-only, no L1 fill; zero-reuse stream)

#define BT    1024      // B*T
#define DEPTH 8
#define V     32000
#define V4    (V / 4)   // 8000 float4 per (b,t,d) row
#define NTHR  320       // 10 warps; 25 * 320 == 8000 exactly

__global__ __launch_bounds__(NTHR) void tokentree_kernel(
    const float4* __restrict__ x,   // (BT, DEPTH, V4)
    const float*  __restrict__ w,   // (DEPTH,)
    const float*  __restrict__ bias,// (1,)
    float4*       __restrict__ out) // (BT, V4)
{
    const int v4 = blockIdx.x * NTHR + threadIdx.x;   // always < 8000
    const int bt = blockIdx.y;

    // Weights + bias: tiny, cache-resident after first warp.
    float w0 = __ldg(&w[0]), w1 = __ldg(&w[1]), w2 = __ldg(&w[2]), w3 = __ldg(&w[3]);
    float w4 = __ldg(&w[4]), w5 = __ldg(&w[5]), w6 = __ldg(&w[6]), w7 = __ldg(&w[7]);
    float b0 = __ldg(&bias[0]);

    const float4* xp = x + (size_t)bt * DEPTH * V4 + v4;

    // 8 independent coalesced 128B-per-warp loads, L2-only, front-batched.
    float4 x0 = __ldcg(xp + 0 * V4);
    float4 x1 = __ldcg(xp + 1 * V4);
    float4 x2 = __ldcg(xp + 2 * V4);
    float4 x3 = __ldcg(xp + 3 * V4);
    float4 x4 = __ldcg(xp + 4 * V4);
    float4 x5 = __ldcg(xp + 5 * V4);
    float4 x6 = __ldcg(xp + 6 * V4);
    float4 x7 = __ldcg(xp + 7 * V4);

    float4 acc;
    acc.x = b0; acc.y = b0; acc.z = b0; acc.w = b0;

    acc.x = fmaf(w0, x0.x, acc.x); acc.y = fmaf(w0, x0.y, acc.y);
    acc.z = fmaf(w0, x0.z, acc.z); acc.w = fmaf(w0, x0.w, acc.w);
    acc.x = fmaf(w1, x1.x, acc.x); acc.y = fmaf(w1, x1.y, acc.y);
    acc.z = fmaf(w1, x1.z, acc.z); acc.w = fmaf(w1, x1.w, acc.w);
    acc.x = fmaf(w2, x2.x, acc.x); acc.y = fmaf(w2, x2.y, acc.y);
    acc.z = fmaf(w2, x2.z, acc.z); acc.w = fmaf(w2, x2.w, acc.w);
    acc.x = fmaf(w3, x3.x, acc.x); acc.y = fmaf(w3, x3.y, acc.y);
    acc.z = fmaf(w3, x3.z, acc.z); acc.w = fmaf(w3, x3.w, acc.w);
    acc.x = fmaf(w4, x4.x, acc.x); acc.y = fmaf(w4, x4.y, acc.y);
    acc.z = fmaf(w4, x4.z, acc.z); acc.w = fmaf(w4, x4.w, acc.w);
    acc.x = fmaf(w5, x5.x, acc.x); acc.y = fmaf(w5, x5.y, acc.y);
    acc.z = fmaf(w5, x5.z, acc.z); acc.w = fmaf(w5, x5.w, acc.w);
    acc.x = fmaf(w6, x6.x, acc.x); acc.y = fmaf(w6, x6.y, acc.y);
    acc.z = fmaf(w6, x6.z, acc.z); acc.w = fmaf(w6, x6.w, acc.w);
    acc.x = fmaf(w7, x7.x, acc.x); acc.y = fmaf(w7, x7.y, acc.y);
    acc.z = fmaf(w7, x7.z, acc.z); acc.w = fmaf(w7, x7.w, acc.w);

    // Write-through store: bursty DRAM writes, no dirty-eviction
    // interleaving with the read-fill stream (measured +0.4% BW).
    __stwt(out + (size_t)bt * V4 + v4, acc);
}

extern "C" void kernel_launch(void* const* d_in, const int* in_sizes, int n_in,
                              void* d_out, int out_size) {
    const float4* x    = (const float4*)d_in[0];
    const float*  w    = (const float*)d_in[1];
    const float*  bias = (const float*)d_in[2];
    float4*       out  = (float4*)d_out;

    dim3 block(NTHR);
    dim3 grid(V4 / NTHR, BT);   // (25, 1024) — exact cover, no tails
    tokentree_kernel<<<grid, block>>>(x, w, bias, out);
}

// round 10
// speedup vs baseline: 1.0004x; 1.0004x over previous
#include <cuda_runtime.h>
#include <cuda_bf16.h>

// out[b,t,v] = sum_d x[b,t,d,v] * w[d] + bias
// x: (B=2, T=512, D=8, V=32000) fp32 ; w: (8,) ; b: (1,)
//
// FINAL (v6, re-confirmed): pure HBM-stream kernel.
//   - 1 float4 of output per thread; 8 front-batched independent LDG.128
//     per thread (one per depth slice, stride 128KB) -> MLP=8, perfectly
//     coalesced 128B lines per warp.
//   - 256-thread blocks, 32 regs -> 8 CTAs/SM = 64 resident warps (max
//     bytes-in-flight; measured-best occupancy point).
//   - __stwt write-through stores: bursty DRAM writes, no L2 dirty-eviction
//     interleaving with the read stream (measured +0.4% BW, best kernel time).
// Measured: 162.0us kernel, 7227 GB/s = 91.2% DRAM-active; traffic at the
// 1.18 GB theoretical minimum. All structural alternatives (persistent grid,
// 2x/thread batching, __ldcg/__ldcs, constant-mem weights, 320/512-thr
// blocks) bench equal or worse.

#define BT    1024      // B*T
#define DEPTH 8
#define V     32000
#define V4    (V / 4)   // 8000 float4 per (b,t,d) row
#define NTHR  256

__global__ __launch_bounds__(NTHR) void tokentree_kernel(
    const float4* __restrict__ x,   // (BT, DEPTH, V4)
    const float*  __restrict__ w,   // (DEPTH,)
    const float*  __restrict__ bias,// (1,)
    float4*       __restrict__ out) // (BT, V4)
{
    const int v4 = blockIdx.x * NTHR + threadIdx.x;
    if (v4 >= V4) return;
    const int bt = blockIdx.y;

    // Weights + bias: tiny, L1-resident after first warp.
    float w0 = __ldg(&w[0]), w1 = __ldg(&w[1]), w2 = __ldg(&w[2]), w3 = __ldg(&w[3]);
    float w4 = __ldg(&w[4]), w5 = __ldg(&w[5]), w6 = __ldg(&w[6]), w7 = __ldg(&w[7]);
    float b0 = __ldg(&bias[0]);

    const float4* xp = x + (size_t)bt * DEPTH * V4 + v4;

    // 8 independent coalesced 128B-per-warp loads, front-batched -> MLP=8.
    float4 x0 = __ldg(xp + 0 * V4);
    float4 x1 = __ldg(xp + 1 * V4);
    float4 x2 = __ldg(xp + 2 * V4);
    float4 x3 = __ldg(xp + 3 * V4);
    float4 x4 = __ldg(xp + 4 * V4);
    float4 x5 = __ldg(xp + 5 * V4);
    float4 x6 = __ldg(xp + 6 * V4);
    float4 x7 = __ldg(xp + 7 * V4);

    float4 acc;
    acc.x = b0; acc.y = b0; acc.z = b0; acc.w = b0;

    acc.x = fmaf(w0, x0.x, acc.x); acc.y = fmaf(w0, x0.y, acc.y);
    acc.z = fmaf(w0, x0.z, acc.z); acc.w = fmaf(w0, x0.w, acc.w);
    acc.x = fmaf(w1, x1.x, acc.x); acc.y = fmaf(w1, x1.y, acc.y);
    acc.z = fmaf(w1, x1.z, acc.z); acc.w = fmaf(w1, x1.w, acc.w);
    acc.x = fmaf(w2, x2.x, acc.x); acc.y = fmaf(w2, x2.y, acc.y);
    acc.z = fmaf(w2, x2.z, acc.z); acc.w = fmaf(w2, x2.w, acc.w);
    acc.x = fmaf(w3, x3.x, acc.x); acc.y = fmaf(w3, x3.y, acc.y);
    acc.z = fmaf(w3, x3.z, acc.z); acc.w = fmaf(w3, x3.w, acc.w);
    acc.x = fmaf(w4, x4.x, acc.x); acc.y = fmaf(w4, x4.y, acc.y);
    acc.z = fmaf(w4, x4.z, acc.z); acc.w = fmaf(w4, x4.w, acc.w);
    acc.x = fmaf(w5, x5.x, acc.x); acc.y = fmaf(w5, x5.y, acc.y);
    acc.z = fmaf(w5, x5.z, acc.z); acc.w = fmaf(w5, x5.w, acc.w);
    acc.x = fmaf(w6, x6.x, acc.x); acc.y = fmaf(w6, x6.y, acc.y);
    acc.z = fmaf(w6, x6.z, acc.z); acc.w = fmaf(w6, x6.w, acc.w);
    acc.x = fmaf(w7, x7.x, acc.x); acc.y = fmaf(w7, x7.y, acc.y);
    acc.z = fmaf(w7, x7.z, acc.z); acc.w = fmaf(w7, x7.w, acc.w);

    // Write-through store: bursty DRAM writes, no dirty-eviction
    // interleaving with the read-fill stream.
    __stwt(out + (size_t)bt * V4 + v4, acc);
}

extern "C" void kernel_launch(void* const* d_in, const int* in_sizes, int n_in,
                              void* d_out, int out_size) {
    const float4* x    = (const float4*)d_in[0];
    const float*  w    = (const float*)d_in[1];
    const float*  bias = (const float*)d_in[2];
    float4*       out  = (float4*)d_out;

    dim3 block(NTHR);
    dim3 grid((V4 + NTHR - 1) / NTHR, BT);   // (32, 1024)
    tokentree_kernel<<<grid, block>>>(x, w, bias, out);
}